// round 3
// baseline (speedup 1.0000x reference)
#include <cuda_runtime.h>

// Problem: volume [40,40,40,32] f32, M [32,32], P [32,32] -> Nk [59319,32]
//   b = (k1*39 + k2)*39 + k3
//   Nk[b,i] = sum_j x[b,j] * P[i,j] * cos(k1*a_ij) * cos(k2*a_ij) * cos(k3*a_ij)
//   a_ij = 2pi/(i*32+j+2),  x[b,:] = pooled[b,:] @ M^T  (2x2x2 mean pool)
#define NP   39
#define NB   (39*39*39)
#define PI2F 6.2831853071795864769f

typedef unsigned long long ull;

// Scratch
__device__ float g_tab[39 * 1024];   // tab[k][j*32 + i] = cos(k * 2pi / (i*32+j+2))
__device__ float g_PT[1024];         // PT[j*32 + i] = P[i][j]
__device__ float g_MT[1024];         // MT[l*32 + j] = M[j][l]
__device__ float g_x[NB * 32];       // x[b][j]

// ---- f32x2 packed math (sm_103a) -----------------------------------------
__device__ __forceinline__ ull f2_mul(ull a, ull b) {
    ull d; asm("mul.rn.f32x2 %0, %1, %2;" : "=l"(d) : "l"(a), "l"(b)); return d;
}
__device__ __forceinline__ ull f2_fma(ull a, ull b, ull c) {
    ull d; asm("fma.rn.f32x2 %0, %1, %2, %3;" : "=l"(d) : "l"(a), "l"(b), "l"(c)); return d;
}
__device__ __forceinline__ ull f2_pack(float x) {
    ull d; asm("mov.b64 %0, {%1, %1};" : "=l"(d) : "f"(x)); return d;
}
__device__ __forceinline__ float2 f2_unpack(ull v) {
    float2 r; asm("mov.b64 {%0, %1}, %2;" : "=f"(r.x), "=f"(r.y) : "l"(v)); return r;
}

// ---------------------------------------------------------------------------
// Kernel 0: cos table + transposed P/M.  grid (4,40) x 256 threads.
// blockIdx.y in [0,39): table rows; blockIdx.y==39: PT/MT.
// ---------------------------------------------------------------------------
__global__ void k_pre(const float* __restrict__ M, const float* __restrict__ P) {
    int k = blockIdx.y;
    int t = blockIdx.x * 256 + threadIdx.x;   // t = j*32 + i
    if (k < 39) {
        int i = t & 31;
        int j = t >> 5;
        float invp = PI2F / (float)(i * 32 + j + 2);
        g_tab[k * 1024 + t] = cosf((float)k * invp);
    } else {
        int src = (t & 31) * 32 + (t >> 5);
        g_PT[t] = P[src];
        g_MT[t] = M[src];
    }
}

// ---------------------------------------------------------------------------
// Kernel 1: 2x2x2 mean pool + x = pooled @ M^T.  One block per (k1,k2).
// Stages the 4 needed volume rows in smem (halves global traffic).
// ---------------------------------------------------------------------------
__global__ void __launch_bounds__(320) k_x(const float* __restrict__ vol) {
    __shared__ float vol_s[4 * 1280];     // [dh][w*32 + c], 20KB
    __shared__ float pooled_s[NP * 36];   // stride 36: 16B aligned, bank-skewed
    __shared__ float MT_s[1024];

    const int k2 = blockIdx.x;
    const int k1 = blockIdx.y;
    const int tid = threadIdx.x;

    for (int t = tid; t < 1024; t += 320) MT_s[t] = g_MT[t];

    // Stage rows (k1+dd, k2+hh, 0..39, :) as float4
    for (int f4 = tid; f4 < 1280; f4 += 320) {
        int dh = f4 / 320;                 // dd*2 + hh
        int r  = f4 - dh * 320;            // w*8 + cq
        const float4* src = (const float4*)(vol +
            (((k1 + (dh >> 1)) * 40) + (k2 + (dh & 1))) * 1280) + r;
        *((float4*)vol_s + dh * 320 + r) = *src;
    }
    __syncthreads();

    // Pool: thread = (k3, cq)
    if (tid < 312) {
        int k3 = tid >> 3;
        int cq = tid & 7;
        float4 s = make_float4(0.f, 0.f, 0.f, 0.f);
#pragma unroll
        for (int dh = 0; dh < 4; dh++)
#pragma unroll
            for (int ww = 0; ww < 2; ww++) {
                float4 v = *(const float4*)&vol_s[dh * 1280 + (k3 + ww) * 32 + cq * 4];
                s.x += v.x; s.y += v.y; s.z += v.z; s.w += v.w;
            }
        s.x *= 0.125f; s.y *= 0.125f; s.z *= 0.125f; s.w *= 0.125f;
        *(float4*)&pooled_s[k3 * 36 + cq * 4] = s;
    }
    __syncthreads();

    // x[b][j] = sum_l M[j][l] * pooled[l]
    if (tid < 312) {
        int k3 = tid >> 3;
        int jq = tid & 7;
        float a0 = 0.f, a1 = 0.f, a2 = 0.f, a3 = 0.f;
#pragma unroll
        for (int l = 0; l < 32; l++) {
            float p = pooled_s[k3 * 36 + l];
            float4 m4 = *(const float4*)&MT_s[l * 32 + jq * 4];
            a0 += p * m4.x; a1 += p * m4.y; a2 += p * m4.z; a3 += p * m4.w;
        }
        int b = (k1 * NP + k2) * NP + k3;
        *(float4*)&g_x[b * 32 + jq * 4] = make_float4(a0, a1, a2, a3);
    }
}

// ---------------------------------------------------------------------------
// Kernel 2: main contraction, register-blocked 4(k2) x 4(k3) x 4(i) per thread,
// packed f32x2 FMA core.
// grid (10, 39): blockIdx.x = k2 tile of 4, blockIdx.y = k1.
// 96 threads; active tid<80: iq = tid&7 (i quad), k3g = tid>>3 (k3 group of 4).
// ---------------------------------------------------------------------------
#define XSTRIDE 44   // k3 stride pad: 16B-aligned vec loads, skewed banks

__global__ void __launch_bounds__(96) k_main(float* __restrict__ out) {
    __shared__ float A_s[4 * 1024];            // A[c][j*32+i] = P*c1*c2   (16KB)
    __shared__ float x_s[4 * 32 * XSTRIDE];    // x[c][j][k3]              (22KB)

    const int k1  = blockIdx.y;
    const int k2b = blockIdx.x * 4;
    const int tid = threadIdx.x;

    // Stage A (zero for k2 >= 39 so accs stay clean)
    for (int idx = tid; idx < 4096; idx += 96) {
        int c = idx >> 10;
        int t = idx & 1023;
        float a = 0.f;
        if (k2b + c < NP)
            a = g_PT[t] * g_tab[k1 * 1024 + t] * g_tab[(k2b + c) * 1024 + t];
        A_s[idx] = a;
    }
    // Stage x transposed to [c][j][k3]; zero invalid (k3=39, k2>=39).
    // idx = c*1280 + k3*32 + j  (FIXED decomposition: /1280, not >>11)
    for (int idx = tid; idx < 4 * 40 * 32; idx += 96) {
        int c  = idx / 1280;
        int r  = idx - c * 1280;
        int k3 = r >> 5;
        int j  = r & 31;
        float xv = 0.f;
        if (k3 < NP && (k2b + c) < NP)
            xv = g_x[(((k1 * NP) + k2b + c) * NP + k3) * 32 + j];
        x_s[c * (32 * XSTRIDE) + j * XSTRIDE + k3] = xv;
    }
    __syncthreads();

    if (tid < 80) {
        const int iq  = tid & 7;
        const int k3g = tid >> 3;           // 0..9

        // c3 row pointers (clamp k3=39 -> 38; its x is zeroed so acc stays 0)
        const ulonglong2* c3p[4];
#pragma unroll
        for (int t = 0; t < 4; t++) {
            int k3 = k3g * 4 + t; if (k3 > 38) k3 = 38;
            c3p[t] = (const ulonglong2*)(g_tab + k3 * 1024 + iq * 4);
        }
        const ulonglong2* ap = (const ulonglong2*)(A_s + iq * 4);
        const float4*     xp4 = (const float4*)(x_s + k3g * 4);

        ull acc[4][4][2];
#pragma unroll
        for (int c = 0; c < 4; c++)
#pragma unroll
            for (int t = 0; t < 4; t++) { acc[c][t][0] = 0ull; acc[c][t][1] = 0ull; }

#pragma unroll 4
        for (int j = 0; j < 32; j++) {
            ulonglong2 c3[4];
#pragma unroll
            for (int t = 0; t < 4; t++) c3[t] = c3p[t][j * 8];

            ulonglong2 a[4];
            float4     xf[4];
#pragma unroll
            for (int c = 0; c < 4; c++) {
                a[c]  = ap[c * 256 + j * 8];                      // A[c][j][iq*4..]
                xf[c] = xp4[(c * (32 * XSTRIDE) + j * XSTRIDE) >> 2];
            }
#pragma unroll
            for (int c = 0; c < 4; c++) {
                float xv[4] = {xf[c].x, xf[c].y, xf[c].z, xf[c].w};
#pragma unroll
                for (int t = 0; t < 4; t++) {
                    ull xd = f2_pack(xv[t]);
                    acc[c][t][0] = f2_fma(f2_mul(a[c].x, xd), c3[t].x, acc[c][t][0]);
                    acc[c][t][1] = f2_fma(f2_mul(a[c].y, xd), c3[t].y, acc[c][t][1]);
                }
            }
        }

        // Store
#pragma unroll
        for (int c = 0; c < 4; c++) {
            if (k2b + c >= NP) continue;
#pragma unroll
            for (int t = 0; t < 4; t++) {
                int k3 = k3g * 4 + t;
                if (k3 >= NP) continue;
                int b = ((k1 * NP) + k2b + c) * NP + k3;
                float2 lo = f2_unpack(acc[c][t][0]);
                float2 hi = f2_unpack(acc[c][t][1]);
                *(float4*)&out[b * 32 + iq * 4] = make_float4(lo.x, lo.y, hi.x, hi.y);
            }
        }
    }
}

// ---------------------------------------------------------------------------
extern "C" void kernel_launch(void* const* d_in, const int* in_sizes, int n_in,
                              void* d_out, int out_size) {
    const float* vol = (const float*)d_in[0];
    const float* M   = (const float*)d_in[1];
    const float* P   = (const float*)d_in[2];
    float* out = (float*)d_out;

    k_pre <<<dim3(4, 40), 256>>>(M, P);
    k_x   <<<dim3(39, 39), 320>>>(vol);
    k_main<<<dim3(10, 39), 96>>>(out);
}

// round 4
// speedup vs baseline: 1.3440x; 1.3440x over previous
#include <cuda_runtime.h>

// Problem: volume [40,40,40,32] f32, M [32,32], P [32,32] -> Nk [59319,32]
//   b = (k1*39 + k2)*39 + k3
//   Nk[b,i] = sum_j x[b,j] * P[i,j] * cos(k1*a_ij) * cos(k2*a_ij) * cos(k3*a_ij)
//   a_ij = 2pi/(i*32+j+2),  x[b,:] = pooled[b,:] @ M^T  (2x2x2 mean pool)
#define NP   39
#define NB   (39*39*39)
#define PI2F 6.2831853071795864769f

typedef unsigned long long ull;

// Scratch
__device__ float g_tab[39 * 1024];   // tab[k][j*32 + i] = cos(k * 2pi / (i*32+j+2))
__device__ float g_PT[1024];         // PT[j*32 + i] = P[i][j]
__device__ float g_MT[1024];         // MT[l*32 + j] = M[j][l]
__device__ float g_x[NB * 32];       // x[b][j]

// ---- f32x2 packed math (sm_103a) -----------------------------------------
__device__ __forceinline__ ull f2_mul(ull a, ull b) {
    ull d; asm("mul.rn.f32x2 %0, %1, %2;" : "=l"(d) : "l"(a), "l"(b)); return d;
}
__device__ __forceinline__ ull f2_fma(ull a, ull b, ull c) {
    ull d; asm("fma.rn.f32x2 %0, %1, %2, %3;" : "=l"(d) : "l"(a), "l"(b), "l"(c)); return d;
}
__device__ __forceinline__ ull f2_pack(float x) {
    ull d; asm("mov.b64 %0, {%1, %1};" : "=l"(d) : "f"(x)); return d;
}
__device__ __forceinline__ float2 f2_unpack(ull v) {
    float2 r; asm("mov.b64 {%0, %1}, %2;" : "=f"(r.x), "=f"(r.y) : "l"(v)); return r;
}

// ---------------------------------------------------------------------------
// Kernel 0: cos table via Chebyshev recurrence + transposed P/M.
// grid 5 x 256: blocks 0-3 cover t=0..1023 (all 39 k per thread), block 4: PT/MT.
// ---------------------------------------------------------------------------
__global__ void k_pre(const float* __restrict__ M, const float* __restrict__ P) {
    int b = blockIdx.x, tid = threadIdx.x;
    if (b < 4) {
        int t = b * 256 + tid;            // t = j*32 + i
        int i = t & 31, j = t >> 5;
        float a  = PI2F / (float)(i * 32 + j + 2);
        float c1 = cosf(a);
        float twoc = 2.0f * c1;
        float cm2 = 1.0f, cm1 = c1;
        g_tab[t]        = 1.0f;           // k=0
        g_tab[1024 + t] = c1;             // k=1
#pragma unroll
        for (int k = 2; k < 39; k++) {
            float ck = twoc * cm1 - cm2;  // cos(k a)
            g_tab[k * 1024 + t] = ck;
            cm2 = cm1; cm1 = ck;
        }
    } else {
#pragma unroll
        for (int q = 0; q < 4; q++) {
            int t = q * 256 + tid;
            int src = (t & 31) * 32 + (t >> 5);
            g_PT[t] = P[src];
            g_MT[t] = M[src];
        }
    }
}

// ---------------------------------------------------------------------------
// Kernel 1: 2x2x2 mean pool + x = pooled @ M^T.  One block per (k1,k2).
// ---------------------------------------------------------------------------
__global__ void __launch_bounds__(320) k_x(const float* __restrict__ vol) {
    __shared__ float vol_s[4 * 1280];     // [dh][w*32 + c], 20KB
    __shared__ float pooled_s[NP * 36];
    __shared__ float MT_s[1024];

    const int k2 = blockIdx.x;
    const int k1 = blockIdx.y;
    const int tid = threadIdx.x;

    for (int t = tid; t < 1024; t += 320) MT_s[t] = g_MT[t];

    for (int f4 = tid; f4 < 1280; f4 += 320) {
        int dh = f4 / 320;
        int r  = f4 - dh * 320;
        const float4* src = (const float4*)(vol +
            (((k1 + (dh >> 1)) * 40) + (k2 + (dh & 1))) * 1280) + r;
        *((float4*)vol_s + dh * 320 + r) = *src;
    }
    __syncthreads();

    if (tid < 312) {
        int k3 = tid >> 3;
        int cq = tid & 7;
        float4 s = make_float4(0.f, 0.f, 0.f, 0.f);
#pragma unroll
        for (int dh = 0; dh < 4; dh++)
#pragma unroll
            for (int ww = 0; ww < 2; ww++) {
                float4 v = *(const float4*)&vol_s[dh * 1280 + (k3 + ww) * 32 + cq * 4];
                s.x += v.x; s.y += v.y; s.z += v.z; s.w += v.w;
            }
        s.x *= 0.125f; s.y *= 0.125f; s.z *= 0.125f; s.w *= 0.125f;
        *(float4*)&pooled_s[k3 * 36 + cq * 4] = s;
    }
    __syncthreads();

    if (tid < 312) {
        int k3 = tid >> 3;
        int jq = tid & 7;
        float a0 = 0.f, a1 = 0.f, a2 = 0.f, a3 = 0.f;
#pragma unroll
        for (int l = 0; l < 32; l++) {
            float p = pooled_s[k3 * 36 + l];
            float4 m4 = *(const float4*)&MT_s[l * 32 + jq * 4];
            a0 += p * m4.x; a1 += p * m4.y; a2 += p * m4.z; a3 += p * m4.w;
        }
        int b = (k1 * NP + k2) * NP + k3;
        *(float4*)&g_x[b * 32 + jq * 4] = make_float4(a0, a1, a2, a3);
    }
}

// ---------------------------------------------------------------------------
// Kernel 2: main contraction.  grid (10, 39), 160 threads = 5 warps, ALL active.
// Thread = (iq = tid&7 -> 4 i values, k3p = tid>>3 -> 2 k3 values), 4 k2 (c).
// Per-thread outputs: 4c x 2t x 4i = 32 floats (16 f32x2 accumulators).
// ---------------------------------------------------------------------------
#define XSTR 40   // x_s k3 stride (floats); rows 160B, float2-aligned loads

__global__ void __launch_bounds__(160) k_main(float* __restrict__ out) {
    __shared__ float A_s[4 * 1024];     // A[c][j*32+i] = P*c1*c2  (16KB)
    __shared__ float x_s[4 * 1280];     // x[c][j*40 + k3]         (20KB)

    const int k1  = blockIdx.y;
    const int k2b = blockIdx.x * 4;
    const int tid = threadIdx.x;

    // Stage A (zero for k2 >= 39)
    for (int idx = tid; idx < 4096; idx += 160) {
        int c = idx >> 10;
        int t = idx & 1023;
        float a = 0.f;
        if (k2b + c < NP)
            a = g_PT[t] * g_tab[k1 * 1024 + t] * g_tab[(k2b + c) * 1024 + t];
        A_s[idx] = a;
    }
    // Stage x transposed to [c][j][k3]; idx = c*1280 + k3*32 + j
    for (int idx = tid; idx < 5120; idx += 160) {
        int c  = idx / 1280;
        int r  = idx - c * 1280;
        int k3 = r >> 5;
        int j  = r & 31;
        float xv = 0.f;
        if (k3 < NP && (k2b + c) < NP)
            xv = g_x[(((k1 * NP) + k2b + c) * NP + k3) * 32 + j];
        x_s[c * 1280 + j * XSTR + k3] = xv;
    }
    __syncthreads();

    const int iq  = tid & 7;
    const int k3p = tid >> 3;            // 0..19; k3 = k3p*2 + t

    const ulonglong2* c3p[2];
#pragma unroll
    for (int t = 0; t < 2; t++) {
        int k3 = k3p * 2 + t; if (k3 > 38) k3 = 38;   // k3=39: x zeroed
        c3p[t] = (const ulonglong2*)(g_tab + k3 * 1024 + iq * 4);
    }
    const ulonglong2* ap = (const ulonglong2*)(A_s + iq * 4);
    const float2*     xp = (const float2*)x_s;

    ull acc[4][2][2];
#pragma unroll
    for (int c = 0; c < 4; c++)
#pragma unroll
        for (int t = 0; t < 2; t++) { acc[c][t][0] = 0ull; acc[c][t][1] = 0ull; }

#pragma unroll 2
    for (int j = 0; j < 32; j++) {
        ulonglong2 c3[2];
#pragma unroll
        for (int t = 0; t < 2; t++) c3[t] = c3p[t][j * 8];

        ulonglong2 a[4];
        float2     xv[4];
#pragma unroll
        for (int c = 0; c < 4; c++) {
            a[c]  = ap[c * 256 + j * 8];                       // A[c][j][iq*4..]
            xv[c] = xp[(c * 1280 + j * XSTR) / 2 + k3p];       // x[c][j][k3p*2..+1]
        }
#pragma unroll
        for (int c = 0; c < 4; c++) {
            ull xd0 = f2_pack(xv[c].x);
            ull xd1 = f2_pack(xv[c].y);
            acc[c][0][0] = f2_fma(f2_mul(a[c].x, xd0), c3[0].x, acc[c][0][0]);
            acc[c][0][1] = f2_fma(f2_mul(a[c].y, xd0), c3[0].y, acc[c][0][1]);
            acc[c][1][0] = f2_fma(f2_mul(a[c].x, xd1), c3[1].x, acc[c][1][0]);
            acc[c][1][1] = f2_fma(f2_mul(a[c].y, xd1), c3[1].y, acc[c][1][1]);
        }
    }

#pragma unroll
    for (int c = 0; c < 4; c++) {
        if (k2b + c >= NP) continue;
#pragma unroll
        for (int t = 0; t < 2; t++) {
            int k3 = k3p * 2 + t;
            if (k3 >= NP) continue;
            int b = ((k1 * NP) + k2b + c) * NP + k3;
            float2 lo = f2_unpack(acc[c][t][0]);
            float2 hi = f2_unpack(acc[c][t][1]);
            *(float4*)&out[b * 32 + iq * 4] = make_float4(lo.x, lo.y, hi.x, hi.y);
        }
    }
}

// ---------------------------------------------------------------------------
extern "C" void kernel_launch(void* const* d_in, const int* in_sizes, int n_in,
                              void* d_out, int out_size) {
    const float* vol = (const float*)d_in[0];
    const float* M   = (const float*)d_in[1];
    const float* P   = (const float*)d_in[2];
    float* out = (float*)d_out;

    k_pre <<<5, 256>>>(M, P);
    k_x   <<<dim3(39, 39), 320>>>(vol);
    k_main<<<dim3(10, 39), 160>>>(out);
}